// round 10
// baseline (speedup 1.0000x reference)
#include <cuda_runtime.h>
#include <cstdint>

// ---------------------------------------------------------------------------
// StableGATModel: 2-layer GAT (heads=2, hid=64) + linear head.
// Strategy: CSR-by-dst built per launch (int atomics only), then all segment
// ops are warp-per-node GATHERS (no float atomics). GEMMs are register-tiled
// fp32. Bias+ELU fused into aggregation epilogue.
// R6 fix: k_final shared tile was [64][36] but staged 128 floats/row ->
// shared OOB -> illegal memory access. Rewritten with provably-bounded tiles.
// ---------------------------------------------------------------------------

constexpr int NN = 100000;
constexpr int NE = 1600000;
constexpr int NB_SCAN = (NN + 1023) / 1024;   // 98

// Scratch (static device globals: allocation-free per harness rules)
__device__ float  g_h[(size_t)NN * 128];   // GEMM output (pre-attention h)
__device__ float  g_x[(size_t)NN * 128];   // activations (ELU(layer out))
__device__ float4 g_elr[NN];               // {el0, el1, er0, er1} per node
__device__ float2 g_p[NE];                 // exp(e) per CSR slot, both heads
__device__ float2 g_sinv[NN];              // 1/(sum+eps) per node per head
__device__ int    g_rowstart[NN + 1];
__device__ int    g_cursor[NN];
__device__ int    g_csrc[NE];              // src node per CSR slot
__device__ int    g_bsum[128];
__device__ int    g_boff[128];

// ------------------------------- CSR build --------------------------------

__global__ void k_hist(const int* __restrict__ dst, int* __restrict__ deg, int e) {
    int i = blockIdx.x * blockDim.x + threadIdx.x;
    if (i < e) atomicAdd(&deg[dst[i]], 1);
}

__global__ void k_scan1(const int* __restrict__ deg, int* __restrict__ incl,
                        int* __restrict__ bsum, int n) {
    __shared__ int sm[1024];
    int t = threadIdx.x;
    int i = blockIdx.x * 1024 + t;
    sm[t] = (i < n) ? deg[i] : 0;
    __syncthreads();
#pragma unroll
    for (int off = 1; off < 1024; off <<= 1) {
        int u = (t >= off) ? sm[t - off] : 0;
        __syncthreads();
        sm[t] += u;
        __syncthreads();
    }
    if (i < n) incl[i] = sm[t];               // goes to rowstart[i+1]
    if (t == 1023) bsum[blockIdx.x] = sm[1023];
}

__global__ void k_scan2(const int* __restrict__ bsum, int* __restrict__ boff,
                        int nb, int* __restrict__ rowstart) {
    if (threadIdx.x == 0) {
        rowstart[0] = 0;
        int run = 0;
        for (int b = 0; b < nb; ++b) { boff[b] = run; run += bsum[b]; }
    }
}

__global__ void k_scan3(int* __restrict__ incl, const int* __restrict__ boff, int n) {
    int i = blockIdx.x * 1024 + threadIdx.x;
    if (i < n) incl[i] += boff[blockIdx.x];
}

__global__ void k_scatter(const int* __restrict__ src, const int* __restrict__ dst,
                          int* __restrict__ cursor, int* __restrict__ csrc, int e) {
    int i = blockIdx.x * blockDim.x + threadIdx.x;
    if (i < e) {
        int slot = atomicAdd(&cursor[dst[i]], 1);
        csrc[slot] = src[i];
    }
}

// ------------------------------- GEMM (N x K) @ (K x 128) ------------------
// BM=64 rows/block, 256 threads. Thread: 8 rows x 4 cols register tile.

template <int K>
__global__ __launch_bounds__(256)
void k_gemm128(const float* __restrict__ A, const float* __restrict__ W,
               float* __restrict__ C, int n) {
    __shared__ float As[32][65];    // [k][row], padded
    __shared__ float Ws[32][128];   // [k][col]
    const int tid = threadIdx.x;
    const int cg  = tid & 31;       // cols 4*cg .. 4*cg+3
    const int rg  = tid >> 5;       // rows 8*rg .. 8*rg+7
    const int brow = blockIdx.x * 64;

    float acc[8][4];
#pragma unroll
    for (int r = 0; r < 8; ++r)
#pragma unroll
        for (int c = 0; c < 4; ++c) acc[r][c] = 0.f;

    for (int k0 = 0; k0 < K; k0 += 32) {
        // A tile: 64 rows x 32 k  (transpose into As[k][r])
#pragma unroll
        for (int pass = 0; pass < 2; ++pass) {
            int r = (tid >> 3) + pass * 32;       // 0..63
            int kq = (tid & 7) * 4;               // 0..28
            int grow = brow + r;
            float4 v = make_float4(0.f, 0.f, 0.f, 0.f);
            if (grow < n) v = *(const float4*)&A[(size_t)grow * K + k0 + kq];
            As[kq + 0][r] = v.x; As[kq + 1][r] = v.y;
            As[kq + 2][r] = v.z; As[kq + 3][r] = v.w;
        }
        // W tile: 32 k x 128 c
#pragma unroll
        for (int i = 0; i < 4; ++i) {
            int idx = tid + i * 256;              // float4 index 0..1023
            int kk = idx >> 5;                    // 0..31
            int cc = (idx & 31) * 4;              // 0..124
            *(float4*)&Ws[kk][cc] = *(const float4*)&W[(size_t)(k0 + kk) * 128 + cc];
        }
        __syncthreads();
#pragma unroll
        for (int k = 0; k < 32; ++k) {
            float4 wv = *(const float4*)&Ws[k][cg * 4];
#pragma unroll
            for (int r = 0; r < 8; ++r) {
                float a = As[k][rg * 8 + r];
                acc[r][0] += a * wv.x; acc[r][1] += a * wv.y;
                acc[r][2] += a * wv.z; acc[r][3] += a * wv.w;
            }
        }
        __syncthreads();
    }
#pragma unroll
    for (int r = 0; r < 8; ++r) {
        int grow = brow + rg * 8 + r;
        if (grow < n) {
            float4 v = make_float4(acc[r][0], acc[r][1], acc[r][2], acc[r][3]);
            *(float4*)&C[(size_t)grow * 128 + cg * 4] = v;
        }
    }
}

// --------------------------- attention precompute ---------------------------
// Warp per node: el_h = sum_f h[n,h,f]*al[h,f], er_h likewise.

__global__ __launch_bounds__(256)
void k_elr(const float* __restrict__ h, const float* __restrict__ al,
           const float* __restrict__ ar, float4* __restrict__ elr, int n) {
    int w = (blockIdx.x * blockDim.x + threadIdx.x) >> 5;
    int lane = threadIdx.x & 31;
    if (w >= n) return;
    int head = lane >> 4;
    int c = (lane & 15) * 4;
    float4 hv  = *(const float4*)&h[(size_t)w * 128 + head * 64 + c];
    float4 alv = *(const float4*)&al[head * 64 + c];
    float4 arv = *(const float4*)&ar[head * 64 + c];
    float el = hv.x * alv.x + hv.y * alv.y + hv.z * alv.z + hv.w * alv.w;
    float er = hv.x * arv.x + hv.y * arv.y + hv.z * arv.z + hv.w * arv.w;
#pragma unroll
    for (int m = 8; m >= 1; m >>= 1) {
        el += __shfl_xor_sync(0xffffffffu, el, m);
        er += __shfl_xor_sync(0xffffffffu, er, m);
    }
    float el1 = __shfl_sync(0xffffffffu, el, 16);
    float er1 = __shfl_sync(0xffffffffu, er, 16);
    if (lane == 0) elr[w] = make_float4(el, el1, er, er1);
}

// ------------------------- softmax numerators + 1/sum -----------------------
// Warp per dst node. No max-subtraction needed: |e| is O(10) so exp() is safe
// and exp(e)/sum exp(e) is exactly the shifted softmax.

__global__ __launch_bounds__(256)
void k_softmax(const float4* __restrict__ elr, const int* __restrict__ rowstart,
               const int* __restrict__ csrc, float2* __restrict__ p,
               float2* __restrict__ sinv, int n) {
    int w = (blockIdx.x * blockDim.x + threadIdx.x) >> 5;
    int lane = threadIdx.x & 31;
    if (w >= n) return;
    int st = rowstart[w], en = rowstart[w + 1];
    float4 me = elr[w];                      // .z/.w = er(dst) per head
    const float2* el2 = (const float2*)elr;  // el pair = element 2*node
    float s0 = 0.f, s1 = 0.f;
    for (int j = st + lane; j < en; j += 32) {
        int sj = csrc[j];
        float2 ev = el2[(size_t)sj * 2];     // {el0, el1} of src
        float e0 = ev.x + me.z;  e0 = (e0 > 0.f) ? e0 : 0.2f * e0;
        float e1 = ev.y + me.w;  e1 = (e1 > 0.f) ? e1 : 0.2f * e1;
        float p0 = __expf(e0), p1 = __expf(e1);
        p[j] = make_float2(p0, p1);
        s0 += p0; s1 += p1;
    }
#pragma unroll
    for (int m = 16; m >= 1; m >>= 1) {
        s0 += __shfl_xor_sync(0xffffffffu, s0, m);
        s1 += __shfl_xor_sync(0xffffffffu, s1, m);
    }
    if (lane == 0)
        sinv[w] = make_float2(1.f / (s0 + 1e-9f), 1.f / (s1 + 1e-9f));
}

// ---------------------- aggregation + bias + ELU (fused) --------------------
// Warp per dst node; lane l covers feature cols 4l..4l+3 (head = l>>4).

__global__ __launch_bounds__(256)
void k_aggregate(const float* __restrict__ h, const int* __restrict__ rowstart,
                 const int* __restrict__ csrc, const float2* __restrict__ p,
                 const float2* __restrict__ sinv, const float* __restrict__ bias,
                 float* __restrict__ out, int n) {
    int w = (blockIdx.x * blockDim.x + threadIdx.x) >> 5;
    int lane = threadIdx.x & 31;
    if (w >= n) return;
    int st = rowstart[w], en = rowstart[w + 1];
    float2 si = sinv[w];
    int head = lane >> 4;
    float sih = head ? si.y : si.x;
    float4 acc = make_float4(0.f, 0.f, 0.f, 0.f);

    int j = st;
    for (; j + 1 < en; j += 2) {          // unroll 2: two gathers in flight
        int s0 = csrc[j], s1 = csrc[j + 1];
        float2 pv0 = p[j], pv1 = p[j + 1];
        float4 h0 = *(const float4*)&h[(size_t)s0 * 128 + lane * 4];
        float4 h1 = *(const float4*)&h[(size_t)s1 * 128 + lane * 4];
        float a0 = (head ? pv0.y : pv0.x) * sih;
        float a1 = (head ? pv1.y : pv1.x) * sih;
        acc.x += a0 * h0.x + a1 * h1.x;
        acc.y += a0 * h0.y + a1 * h1.y;
        acc.z += a0 * h0.z + a1 * h1.z;
        acc.w += a0 * h0.w + a1 * h1.w;
    }
    if (j < en) {
        int s0 = csrc[j];
        float2 pv0 = p[j];
        float4 h0 = *(const float4*)&h[(size_t)s0 * 128 + lane * 4];
        float a0 = (head ? pv0.y : pv0.x) * sih;
        acc.x += a0 * h0.x; acc.y += a0 * h0.y;
        acc.z += a0 * h0.z; acc.w += a0 * h0.w;
    }
    float4 bv = *(const float4*)&bias[lane * 4];
    acc.x += bv.x; acc.y += bv.y; acc.z += bv.z; acc.w += bv.w;
    // ELU
    acc.x = (acc.x > 0.f) ? acc.x : expm1f(acc.x);
    acc.y = (acc.y > 0.f) ? acc.y : expm1f(acc.y);
    acc.z = (acc.z > 0.f) ? acc.z : expm1f(acc.z);
    acc.w = (acc.w > 0.f) ? acc.w : expm1f(acc.w);
    *(float4*)&out[(size_t)w * 128 + lane * 4] = acc;
}

// ------------------------------- final linear -------------------------------
// [N,128] @ [128,16] + bl. 16 nodes/block, 256 threads = (node, outcol) grid.
// Ws padded to 17 cols: lanes 0..15 hit 16 consecutive banks, lanes 16..31
// broadcast the same addresses -> conflict-free.

__global__ __launch_bounds__(256)
void k_final(const float* __restrict__ x, const float* __restrict__ Wl,
             const float* __restrict__ bl, float* __restrict__ y, int n) {
    __shared__ float Ws[128][17];    // [k][col]
    __shared__ float xs[16][128];    // [node][k]
    int tid = threadIdx.x;
    for (int i = tid; i < 2048; i += 256)
        Ws[i >> 4][i & 15] = Wl[i];
    int base = blockIdx.x * 16;
    for (int i = tid; i < 512; i += 256) {       // 16 nodes * 32 float4
        int nd = i >> 5;                          // 0..15
        int kq = (i & 31) * 4;                    // 0..124
        int g = base + nd;
        float4 v = make_float4(0.f, 0.f, 0.f, 0.f);
        if (g < n) v = *(const float4*)&x[(size_t)g * 128 + kq];
        *(float4*)&xs[nd][kq] = v;
    }
    __syncthreads();
    int nd = tid >> 4;       // 0..15
    int c  = tid & 15;       // 0..15
    float acc = bl[c];
#pragma unroll 16
    for (int k = 0; k < 128; ++k)
        acc += xs[nd][k] * Ws[k][c];
    int g = base + nd;
    if (g < n) y[(size_t)g * 16 + c] = acc;
}

// --------------------------------- launch ----------------------------------

extern "C" void kernel_launch(void* const* d_in, const int* in_sizes, int n_in,
                              void* d_out, int out_size) {
    const float* features = (const float*)d_in[0];
    const int*   src      = (const int*)  d_in[1];
    const int*   dst      = (const int*)  d_in[2];
    const float* W1  = (const float*)d_in[3];
    const float* al1 = (const float*)d_in[4];
    const float* ar1 = (const float*)d_in[5];
    const float* b1  = (const float*)d_in[6];
    const float* W2  = (const float*)d_in[7];
    const float* al2 = (const float*)d_in[8];
    const float* ar2 = (const float*)d_in[9];
    const float* b2  = (const float*)d_in[10];
    const float* Wl  = (const float*)d_in[11];
    const float* bl  = (const float*)d_in[12];
    float* out = (float*)d_out;

    void *p_h, *p_x, *p_elr, *p_p, *p_sinv, *p_rs, *p_cur, *p_csrc, *p_bsum, *p_boff;
    cudaGetSymbolAddress(&p_h,    g_h);
    cudaGetSymbolAddress(&p_x,    g_x);
    cudaGetSymbolAddress(&p_elr,  g_elr);
    cudaGetSymbolAddress(&p_p,    g_p);
    cudaGetSymbolAddress(&p_sinv, g_sinv);
    cudaGetSymbolAddress(&p_rs,   g_rowstart);
    cudaGetSymbolAddress(&p_cur,  g_cursor);
    cudaGetSymbolAddress(&p_csrc, g_csrc);
    cudaGetSymbolAddress(&p_bsum, g_bsum);
    cudaGetSymbolAddress(&p_boff, g_boff);

    float*  h_buf  = (float*)p_h;
    float*  x_buf  = (float*)p_x;
    float4* elr    = (float4*)p_elr;
    float2* pbuf   = (float2*)p_p;
    float2* sinv   = (float2*)p_sinv;
    int*    rs     = (int*)p_rs;
    int*    cur    = (int*)p_cur;
    int*    csrc   = (int*)p_csrc;
    int*    bsum   = (int*)p_bsum;
    int*    boff   = (int*)p_boff;

    const int EB = (NE + 255) / 256;          // 6250
    const int GB = (NN + 63) / 64;            // 1563
    const int WB = (NN * 32 + 255) / 256;     // 12500 (warp-per-node)
    const int FB = (NN + 15) / 16;            // 6250

    // ---- CSR build (by dst) ----
    cudaMemsetAsync(cur, 0, NN * sizeof(int));
    k_hist<<<EB, 256>>>(dst, cur, NE);
    k_scan1<<<NB_SCAN, 1024>>>(cur, rs + 1, bsum, NN);
    k_scan2<<<1, 32>>>(bsum, boff, NB_SCAN, rs);
    k_scan3<<<NB_SCAN, 1024>>>(rs + 1, boff, NN);
    cudaMemcpyAsync(cur, rs, NN * sizeof(int), cudaMemcpyDeviceToDevice);
    k_scatter<<<EB, 256>>>(src, dst, cur, csrc, NE);

    // ---- Layer 1 ----
    k_gemm128<256><<<GB, 256>>>(features, W1, h_buf, NN);
    k_elr<<<WB, 256>>>(h_buf, al1, ar1, elr, NN);
    k_softmax<<<WB, 256>>>(elr, rs, csrc, pbuf, sinv, NN);
    k_aggregate<<<WB, 256>>>(h_buf, rs, csrc, pbuf, sinv, b1, x_buf, NN);

    // ---- Layer 2 ----
    k_gemm128<128><<<GB, 256>>>(x_buf, W2, h_buf, NN);
    k_elr<<<WB, 256>>>(h_buf, al2, ar2, elr, NN);
    k_softmax<<<WB, 256>>>(elr, rs, csrc, pbuf, sinv, NN);
    k_aggregate<<<WB, 256>>>(h_buf, rs, csrc, pbuf, sinv, b2, x_buf, NN);

    // ---- Output head ----
    k_final<<<FB, 256>>>(x_buf, Wl, bl, out, NN);
}

// round 14
// speedup vs baseline: 1.4190x; 1.4190x over previous
#include <cuda_runtime.h>
#include <cstdint>

// ---------------------------------------------------------------------------
// StableGATModel: 2-layer GAT (heads=2, hid=64) + linear head.
// R13 -> R14: tcgen05 is sm_103a-gated and the harness builds PTX for plain
// sm_103 -> use baseline-ISA tensor cores instead: mma.sync m16n8k8 tf32
// (sm_80+ PTX, legacy HMMA pipe). 128x128 block tile, 8 warps (4x2), warp
// tile 32x64, BK=32, conflict-free smem pads, cvt.rna.tf32 staging.
// el/er attention dots fused into the GEMM epilogue (k_elr deleted, no W
// transpose needed: B operand is W's native [K][128] layout).
// Edge phase (CSR gather softmax/aggregate) unchanged from passing R10.
// ---------------------------------------------------------------------------

constexpr int NN = 100000;
constexpr int NE = 1600000;
constexpr int NB_SCAN = (NN + 1023) / 1024;   // 98

// Scratch (static device globals: allocation-free per harness rules)
__device__ float  g_h[(size_t)NN * 128];
__device__ float  g_x[(size_t)NN * 128];
__device__ float4 g_elr[NN];               // {el0, el1, er0, er1}
__device__ float2 g_p[NE];
__device__ float2 g_sinv[NN];
__device__ int    g_rowstart[NN + 1];
__device__ int    g_cursor[NN];
__device__ int    g_csrc[NE];
__device__ int    g_bsum[128];
__device__ int    g_boff[128];

// ----------------------------- PTX helpers ---------------------------------

__device__ __forceinline__ uint32_t cvt_tf32(float v) {
    uint32_t r; asm("cvt.rna.tf32.f32 %0, %1;" : "=r"(r) : "f"(v)); return r;
}

__device__ __forceinline__ void mma_tf32(float* c, const uint32_t* a,
                                         uint32_t b0, uint32_t b1) {
    asm volatile(
        "mma.sync.aligned.m16n8k8.row.col.f32.tf32.tf32.f32 "
        "{%0,%1,%2,%3}, {%4,%5,%6,%7}, {%8,%9}, {%0,%1,%2,%3};"
        : "+f"(c[0]), "+f"(c[1]), "+f"(c[2]), "+f"(c[3])
        : "r"(a[0]), "r"(a[1]), "r"(a[2]), "r"(a[3]), "r"(b0), "r"(b1));
}

// ------------------------------- CSR build --------------------------------

__global__ void k_hist(const int* __restrict__ dst, int* __restrict__ deg, int e) {
    int i = blockIdx.x * blockDim.x + threadIdx.x;
    if (i < e) atomicAdd(&deg[dst[i]], 1);
}

__global__ void k_scan1(const int* __restrict__ deg, int* __restrict__ incl,
                        int* __restrict__ bsum, int n) {
    __shared__ int sm[1024];
    int t = threadIdx.x;
    int i = blockIdx.x * 1024 + t;
    sm[t] = (i < n) ? deg[i] : 0;
    __syncthreads();
#pragma unroll
    for (int off = 1; off < 1024; off <<= 1) {
        int u = (t >= off) ? sm[t - off] : 0;
        __syncthreads();
        sm[t] += u;
        __syncthreads();
    }
    if (i < n) incl[i] = sm[t];
    if (t == 1023) bsum[blockIdx.x] = sm[1023];
}

__global__ void k_scan2(const int* __restrict__ bsum, int* __restrict__ boff,
                        int nb, int* __restrict__ rowstart) {
    if (threadIdx.x == 0) {
        rowstart[0] = 0;
        int run = 0;
        for (int b = 0; b < nb; ++b) { boff[b] = run; run += bsum[b]; }
    }
}

__global__ void k_scan3(int* __restrict__ incl, const int* __restrict__ boff, int n) {
    int i = blockIdx.x * 1024 + threadIdx.x;
    if (i < n) incl[i] += boff[blockIdx.x];
}

__global__ void k_scatter(const int* __restrict__ src, const int* __restrict__ dst,
                          int* __restrict__ cursor, int* __restrict__ csrc, int e) {
    int i = blockIdx.x * blockDim.x + threadIdx.x;
    if (i < e) {
        int slot = atomicAdd(&cursor[dst[i]], 1);
        csrc[slot] = src[i];
    }
}

// ------------------- tf32 mma.sync GEMM + fused elr epilogue ----------------
// C[128 x 128] = A[128 x K] @ W[K x 128].  8 warps: (wm 0..3, wn 0..1),
// warp tile 32 rows x 64 cols.  wn == head index -> full el/er per warp.
//
// Fragment maps (m16n8k8, row.col):
//   a0=A[g][t4] a1=A[g+8][t4] a2=A[g][t4+4] a3=A[g+8][t4+4]
//   b0=B[t4][g] b1=B[t4+4][g]      (B = W[k][n], "col" = n-major fragment)
//   c0=C[g][2*t4] c1=C[g][2*t4+1] c2=C[g+8][2*t4] c3=C[g+8][2*t4+1]
// Smem pads: As rows 36 floats -> bank 4*row+k (unique over 8x4 lanes);
//            Ws rows 136 floats -> bank 8*k+n (unique over 4x8 lanes).

template <int K>
__global__ __launch_bounds__(256)
void k_gemm_mma(const float* __restrict__ A, const float* __restrict__ W,
                const float* __restrict__ al, const float* __restrict__ ar,
                float* __restrict__ C, float4* __restrict__ elr, int n)
{
    __shared__ float As[128][36];   // [row][k], 144 B/row (16B aligned)
    __shared__ float Ws[32][136];   // [k][n],  544 B/row (16B aligned)

    const int tid  = threadIdx.x;
    const int w    = tid >> 5;
    const int lane = tid & 31;
    const int wm   = w >> 1;        // 0..3
    const int wn   = w & 1;         // 0..1 (== head)
    const int gid  = lane >> 2;     // 0..7
    const int t4   = lane & 3;      // 0..3
    const int brow = blockIdx.x * 128;

    float acc[2][8][4];
#pragma unroll
    for (int mt = 0; mt < 2; ++mt)
#pragma unroll
        for (int nt = 0; nt < 8; ++nt)
#pragma unroll
            for (int i = 0; i < 4; ++i) acc[mt][nt][i] = 0.f;

    for (int k0 = 0; k0 < K; k0 += 32) {
        // stage A tile: 128 rows x 32 k  (1024 float4, 4/thread)
#pragma unroll
        for (int it = 0; it < 4; ++it) {
            int idx = tid + it * 256;
            int row = idx >> 3;
            int q   = (idx & 7) * 4;
            float4 v = make_float4(0.f, 0.f, 0.f, 0.f);
            if (brow + row < n)
                v = *(const float4*)&A[(size_t)(brow + row) * K + k0 + q];
            uint4 t;
            t.x = cvt_tf32(v.x); t.y = cvt_tf32(v.y);
            t.z = cvt_tf32(v.z); t.w = cvt_tf32(v.w);
            *(uint4*)&As[row][q] = t;
        }
        // stage B tile: 32 k x 128 n  (1024 float4, 4/thread) from W directly
#pragma unroll
        for (int it = 0; it < 4; ++it) {
            int idx = tid + it * 256;
            int kk = idx >> 5;
            int nn = (idx & 31) * 4;
            float4 v = *(const float4*)&W[(size_t)(k0 + kk) * 128 + nn];
            uint4 t;
            t.x = cvt_tf32(v.x); t.y = cvt_tf32(v.y);
            t.z = cvt_tf32(v.z); t.w = cvt_tf32(v.w);
            *(uint4*)&Ws[kk][nn] = t;
        }
        __syncthreads();

#pragma unroll
        for (int ks = 0; ks < 4; ++ks) {
            const int kb = ks * 8;
            uint32_t af[2][4];
#pragma unroll
            for (int mt = 0; mt < 2; ++mt) {
                int r0 = wm * 32 + mt * 16 + gid;
                af[mt][0] = __float_as_uint(As[r0    ][kb + t4    ]);
                af[mt][1] = __float_as_uint(As[r0 + 8][kb + t4    ]);
                af[mt][2] = __float_as_uint(As[r0    ][kb + t4 + 4]);
                af[mt][3] = __float_as_uint(As[r0 + 8][kb + t4 + 4]);
            }
#pragma unroll
            for (int nt = 0; nt < 8; ++nt) {
                int cb = wn * 64 + nt * 8 + gid;
                uint32_t b0 = __float_as_uint(Ws[kb + t4    ][cb]);
                uint32_t b1 = __float_as_uint(Ws[kb + t4 + 4][cb]);
                mma_tf32(acc[0][nt], af[0], b0, b1);
                mma_tf32(acc[1][nt], af[1], b0, b1);
            }
        }
        __syncthreads();
    }

    // ---- epilogue: store C + fused el/er dots ----
    float elp[2][2] = {{0.f, 0.f}, {0.f, 0.f}};   // [mt][half]
    float erp[2][2] = {{0.f, 0.f}, {0.f, 0.f}};
#pragma unroll
    for (int mt = 0; mt < 2; ++mt) {
        int r0 = brow + wm * 32 + mt * 16 + gid;
#pragma unroll
        for (int nt = 0; nt < 8; ++nt) {
            int col = wn * 64 + nt * 8 + t4 * 2;
            float a0 = al[col], a1 = al[col + 1];
            float r0v = ar[col], r1v = ar[col + 1];
            elp[mt][0] += acc[mt][nt][0] * a0  + acc[mt][nt][1] * a1;
            erp[mt][0] += acc[mt][nt][0] * r0v + acc[mt][nt][1] * r1v;
            elp[mt][1] += acc[mt][nt][2] * a0  + acc[mt][nt][3] * a1;
            erp[mt][1] += acc[mt][nt][2] * r0v + acc[mt][nt][3] * r1v;
            if (r0 < n)
                *(float2*)&C[(size_t)r0 * 128 + col] =
                    make_float2(acc[mt][nt][0], acc[mt][nt][1]);
            if (r0 + 8 < n)
                *(float2*)&C[(size_t)(r0 + 8) * 128 + col] =
                    make_float2(acc[mt][nt][2], acc[mt][nt][3]);
        }
    }
    // reduce across the 4 lanes of each quad (same row group)
#pragma unroll
    for (int mt = 0; mt < 2; ++mt)
#pragma unroll
        for (int h = 0; h < 2; ++h) {
            float e = elp[mt][h], r = erp[mt][h];
            e += __shfl_xor_sync(0xffffffffu, e, 1);
            e += __shfl_xor_sync(0xffffffffu, e, 2);
            r += __shfl_xor_sync(0xffffffffu, r, 1);
            r += __shfl_xor_sync(0xffffffffu, r, 2);
            elp[mt][h] = e; erp[mt][h] = r;
        }
    if (t4 == 0) {
#pragma unroll
        for (int mt = 0; mt < 2; ++mt)
#pragma unroll
            for (int h = 0; h < 2; ++h) {
                int row = brow + wm * 32 + mt * 16 + h * 8 + gid;
                if (row < n) {
                    float* e = (float*)&elr[row];
                    e[wn]     = elp[mt][h];   // el{head}
                    e[2 + wn] = erp[mt][h];   // er{head}
                }
            }
    }
}

// ------------------------- softmax numerators + 1/sum -----------------------

__global__ __launch_bounds__(256)
void k_softmax(const float4* __restrict__ elr, const int* __restrict__ rowstart,
               const int* __restrict__ csrc, float2* __restrict__ p,
               float2* __restrict__ sinv, int n) {
    int w = (blockIdx.x * blockDim.x + threadIdx.x) >> 5;
    int lane = threadIdx.x & 31;
    if (w >= n) return;
    int st = rowstart[w], en = rowstart[w + 1];
    float4 me = elr[w];
    const float2* el2 = (const float2*)elr;
    float s0 = 0.f, s1 = 0.f;
    for (int j = st + lane; j < en; j += 32) {
        int sj = csrc[j];
        float2 ev = el2[(size_t)sj * 2];
        float e0 = ev.x + me.z;  e0 = (e0 > 0.f) ? e0 : 0.2f * e0;
        float e1 = ev.y + me.w;  e1 = (e1 > 0.f) ? e1 : 0.2f * e1;
        float p0 = __expf(e0), p1 = __expf(e1);
        p[j] = make_float2(p0, p1);
        s0 += p0; s1 += p1;
    }
#pragma unroll
    for (int m = 16; m >= 1; m >>= 1) {
        s0 += __shfl_xor_sync(0xffffffffu, s0, m);
        s1 += __shfl_xor_sync(0xffffffffu, s1, m);
    }
    if (lane == 0)
        sinv[w] = make_float2(1.f / (s0 + 1e-9f), 1.f / (s1 + 1e-9f));
}

// ---------------------- aggregation + bias + ELU (fused) --------------------

__global__ __launch_bounds__(256)
void k_aggregate(const float* __restrict__ h, const int* __restrict__ rowstart,
                 const int* __restrict__ csrc, const float2* __restrict__ p,
                 const float2* __restrict__ sinv, const float* __restrict__ bias,
                 float* __restrict__ out, int n) {
    int w = (blockIdx.x * blockDim.x + threadIdx.x) >> 5;
    int lane = threadIdx.x & 31;
    if (w >= n) return;
    int st = rowstart[w], en = rowstart[w + 1];
    float2 si = sinv[w];
    int head = lane >> 4;
    float sih = head ? si.y : si.x;
    float4 acc = make_float4(0.f, 0.f, 0.f, 0.f);

    int j = st;
    for (; j + 1 < en; j += 2) {
        int s0 = csrc[j], s1 = csrc[j + 1];
        float2 pv0 = p[j], pv1 = p[j + 1];
        float4 h0 = *(const float4*)&h[(size_t)s0 * 128 + lane * 4];
        float4 h1 = *(const float4*)&h[(size_t)s1 * 128 + lane * 4];
        float a0 = (head ? pv0.y : pv0.x) * sih;
        float a1 = (head ? pv1.y : pv1.x) * sih;
        acc.x += a0 * h0.x + a1 * h1.x;
        acc.y += a0 * h0.y + a1 * h1.y;
        acc.z += a0 * h0.z + a1 * h1.z;
        acc.w += a0 * h0.w + a1 * h1.w;
    }
    if (j < en) {
        int s0 = csrc[j];
        float2 pv0 = p[j];
        float4 h0 = *(const float4*)&h[(size_t)s0 * 128 + lane * 4];
        float a0 = (head ? pv0.y : pv0.x) * sih;
        acc.x += a0 * h0.x; acc.y += a0 * h0.y;
        acc.z += a0 * h0.z; acc.w += a0 * h0.w;
    }
    float4 bv = *(const float4*)&bias[lane * 4];
    acc.x += bv.x; acc.y += bv.y; acc.z += bv.z; acc.w += bv.w;
    acc.x = (acc.x > 0.f) ? acc.x : expm1f(acc.x);
    acc.y = (acc.y > 0.f) ? acc.y : expm1f(acc.y);
    acc.z = (acc.z > 0.f) ? acc.z : expm1f(acc.z);
    acc.w = (acc.w > 0.f) ? acc.w : expm1f(acc.w);
    *(float4*)&out[(size_t)w * 128 + lane * 4] = acc;
}

// ------------------------------- final linear -------------------------------

__global__ __launch_bounds__(256)
void k_final(const float* __restrict__ x, const float* __restrict__ Wl,
             const float* __restrict__ bl, float* __restrict__ y, int n) {
    __shared__ float Ws[128][17];
    __shared__ float xs[16][128];
    int tid = threadIdx.x;
    for (int i = tid; i < 2048; i += 256)
        Ws[i >> 4][i & 15] = Wl[i];
    int base = blockIdx.x * 16;
    for (int i = tid; i < 512; i += 256) {
        int nd = i >> 5;
        int kq = (i & 31) * 4;
        int g = base + nd;
        float4 v = make_float4(0.f, 0.f, 0.f, 0.f);
        if (g < n) v = *(const float4*)&x[(size_t)g * 128 + kq];
        *(float4*)&xs[nd][kq] = v;
    }
    __syncthreads();
    int nd = tid >> 4;
    int c  = tid & 15;
    float acc = bl[c];
#pragma unroll 16
    for (int k = 0; k < 128; ++k)
        acc += xs[nd][k] * Ws[k][c];
    int g = base + nd;
    if (g < n) y[(size_t)g * 16 + c] = acc;
}

// --------------------------------- launch ----------------------------------

extern "C" void kernel_launch(void* const* d_in, const int* in_sizes, int n_in,
                              void* d_out, int out_size) {
    const float* features = (const float*)d_in[0];
    const int*   src      = (const int*)  d_in[1];
    const int*   dst      = (const int*)  d_in[2];
    const float* W1  = (const float*)d_in[3];
    const float* al1 = (const float*)d_in[4];
    const float* ar1 = (const float*)d_in[5];
    const float* b1  = (const float*)d_in[6];
    const float* W2  = (const float*)d_in[7];
    const float* al2 = (const float*)d_in[8];
    const float* ar2 = (const float*)d_in[9];
    const float* b2  = (const float*)d_in[10];
    const float* Wl  = (const float*)d_in[11];
    const float* bl  = (const float*)d_in[12];
    float* out = (float*)d_out;

    void *p_h, *p_x, *p_elr, *p_p, *p_sinv, *p_rs, *p_cur, *p_csrc,
         *p_bsum, *p_boff;
    cudaGetSymbolAddress(&p_h,    g_h);
    cudaGetSymbolAddress(&p_x,    g_x);
    cudaGetSymbolAddress(&p_elr,  g_elr);
    cudaGetSymbolAddress(&p_p,    g_p);
    cudaGetSymbolAddress(&p_sinv, g_sinv);
    cudaGetSymbolAddress(&p_rs,   g_rowstart);
    cudaGetSymbolAddress(&p_cur,  g_cursor);
    cudaGetSymbolAddress(&p_csrc, g_csrc);
    cudaGetSymbolAddress(&p_bsum, g_bsum);
    cudaGetSymbolAddress(&p_boff, g_boff);

    float*  h_buf  = (float*)p_h;
    float*  x_buf  = (float*)p_x;
    float4* elr    = (float4*)p_elr;
    float2* pbuf   = (float2*)p_p;
    float2* sinv   = (float2*)p_sinv;
    int*    rs     = (int*)p_rs;
    int*    cur    = (int*)p_cur;
    int*    csrc   = (int*)p_csrc;
    int*    bsum   = (int*)p_bsum;
    int*    boff   = (int*)p_boff;

    const int EB  = (NE + 255) / 256;         // 6250
    const int WB  = (NN * 32 + 255) / 256;    // 12500 (warp-per-node)
    const int FB  = (NN + 15) / 16;           // 6250
    const int GTC = (NN + 127) / 128;         // 782

    // ---- CSR build (by dst) ----
    cudaMemsetAsync(cur, 0, NN * sizeof(int));
    k_hist<<<EB, 256>>>(dst, cur, NE);
    k_scan1<<<NB_SCAN, 1024>>>(cur, rs + 1, bsum, NN);
    k_scan2<<<1, 32>>>(bsum, boff, NB_SCAN, rs);
    k_scan3<<<NB_SCAN, 1024>>>(rs + 1, boff, NN);
    cudaMemcpyAsync(cur, rs, NN * sizeof(int), cudaMemcpyDeviceToDevice);
    k_scatter<<<EB, 256>>>(src, dst, cur, csrc, NE);

    // ---- Layer 1 ----
    k_gemm_mma<256><<<GTC, 256>>>(features, W1, al1, ar1, h_buf, elr, NN);
    k_softmax<<<WB, 256>>>(elr, rs, csrc, pbuf, sinv, NN);
    k_aggregate<<<WB, 256>>>(h_buf, rs, csrc, pbuf, sinv, b1, x_buf, NN);

    // ---- Layer 2 ----
    k_gemm_mma<128><<<GTC, 256>>>(x_buf, W2, al2, ar2, h_buf, elr, NN);
    k_softmax<<<WB, 256>>>(elr, rs, csrc, pbuf, sinv, NN);
    k_aggregate<<<WB, 256>>>(h_buf, rs, csrc, pbuf, sinv, b2, x_buf, NN);

    // ---- Output head ----
    k_final<<<FB, 256>>>(x_buf, Wl, bl, out, NN);
}

// round 15
// speedup vs baseline: 1.5128x; 1.0662x over previous
#include <cuda_runtime.h>
#include <cuda_fp16.h>
#include <cstdint>

// ---------------------------------------------------------------------------
// StableGATModel: 2-layer GAT (heads=2, hid=64) + linear head.
// R14 -> R15:
//  * h stored as fp16 (half2) by the GEMM epilogue: per-edge gather 512->256B,
//    h table 25.6MB (fully L2-resident). el/er dots still fp32.
//  * softmax+aggregate fused into ONE single-pass kernel via
//    out = (sum p_j h_j) / (sum p_j + 1e-9): p recomputed per lane (1 MUFU),
//    s accumulated redundantly per lane (no shuffles), g_p deleted.
// GEMMs: tf32 mma.sync m16n8k8 (baseline PTX), 128x128 tile, 8 warps.
// ---------------------------------------------------------------------------

constexpr int NN = 100000;
constexpr int NE = 1600000;
constexpr int NB_SCAN = (NN + 1023) / 1024;   // 98

// Scratch (static device globals: allocation-free per harness rules)
__device__ __half2 g_hh[(size_t)NN * 64];  // GEMM output h, fp16 [node][128]
__device__ float   g_x[(size_t)NN * 128];  // activations (fp32)
__device__ float4  g_elr[NN];              // {el0, el1, er0, er1}
__device__ int     g_rowstart[NN + 1];
__device__ int     g_cursor[NN];
__device__ int     g_csrc[NE];
__device__ int     g_bsum[128];
__device__ int     g_boff[128];

// ----------------------------- PTX helpers ---------------------------------

__device__ __forceinline__ uint32_t cvt_tf32(float v) {
    uint32_t r; asm("cvt.rna.tf32.f32 %0, %1;" : "=r"(r) : "f"(v)); return r;
}

__device__ __forceinline__ void mma_tf32(float* c, const uint32_t* a,
                                         uint32_t b0, uint32_t b1) {
    asm volatile(
        "mma.sync.aligned.m16n8k8.row.col.f32.tf32.tf32.f32 "
        "{%0,%1,%2,%3}, {%4,%5,%6,%7}, {%8,%9}, {%0,%1,%2,%3};"
        : "+f"(c[0]), "+f"(c[1]), "+f"(c[2]), "+f"(c[3])
        : "r"(a[0]), "r"(a[1]), "r"(a[2]), "r"(a[3]), "r"(b0), "r"(b1));
}

// ------------------------------- CSR build --------------------------------

__global__ void k_hist(const int* __restrict__ dst, int* __restrict__ deg, int e) {
    int i = blockIdx.x * blockDim.x + threadIdx.x;
    if (i < e) atomicAdd(&deg[dst[i]], 1);
}

__global__ void k_scan1(const int* __restrict__ deg, int* __restrict__ incl,
                        int* __restrict__ bsum, int n) {
    __shared__ int sm[1024];
    int t = threadIdx.x;
    int i = blockIdx.x * 1024 + t;
    sm[t] = (i < n) ? deg[i] : 0;
    __syncthreads();
#pragma unroll
    for (int off = 1; off < 1024; off <<= 1) {
        int u = (t >= off) ? sm[t - off] : 0;
        __syncthreads();
        sm[t] += u;
        __syncthreads();
    }
    if (i < n) incl[i] = sm[t];
    if (t == 1023) bsum[blockIdx.x] = sm[1023];
}

__global__ void k_scan2(const int* __restrict__ bsum, int* __restrict__ boff,
                        int nb, int* __restrict__ rowstart) {
    if (threadIdx.x == 0) {
        rowstart[0] = 0;
        int run = 0;
        for (int b = 0; b < nb; ++b) { boff[b] = run; run += bsum[b]; }
    }
}

__global__ void k_scan3(int* __restrict__ incl, const int* __restrict__ boff, int n) {
    int i = blockIdx.x * 1024 + threadIdx.x;
    if (i < n) incl[i] += boff[blockIdx.x];
}

__global__ void k_scatter(const int* __restrict__ src, const int* __restrict__ dst,
                          int* __restrict__ cursor, int* __restrict__ csrc, int e) {
    int i = blockIdx.x * blockDim.x + threadIdx.x;
    if (i < e) {
        int slot = atomicAdd(&cursor[dst[i]], 1);
        csrc[slot] = src[i];
    }
}

// ------------------- tf32 mma.sync GEMM + fused elr epilogue ----------------
// C[128 x 128] = A[128 x K] @ W[K x 128].  8 warps: (wm 0..3, wn 0..1),
// warp tile 32 rows x 64 cols.  wn == head index -> full el/er per warp.
// Output h stored as half2; el/er computed from fp32 accumulators.

template <int K>
__global__ __launch_bounds__(256)
void k_gemm_mma(const float* __restrict__ A, const float* __restrict__ W,
                const float* __restrict__ al, const float* __restrict__ ar,
                __half2* __restrict__ H, float4* __restrict__ elr, int n)
{
    __shared__ float As[128][36];   // [row][k]
    __shared__ float Ws[32][136];   // [k][n]

    const int tid  = threadIdx.x;
    const int w    = tid >> 5;
    const int lane = tid & 31;
    const int wm   = w >> 1;        // 0..3
    const int wn   = w & 1;         // 0..1 (== head)
    const int gid  = lane >> 2;     // 0..7
    const int t4   = lane & 3;      // 0..3
    const int brow = blockIdx.x * 128;

    float acc[2][8][4];
#pragma unroll
    for (int mt = 0; mt < 2; ++mt)
#pragma unroll
        for (int nt = 0; nt < 8; ++nt)
#pragma unroll
            for (int i = 0; i < 4; ++i) acc[mt][nt][i] = 0.f;

    for (int k0 = 0; k0 < K; k0 += 32) {
#pragma unroll
        for (int it = 0; it < 4; ++it) {
            int idx = tid + it * 256;
            int row = idx >> 3;
            int q   = (idx & 7) * 4;
            float4 v = make_float4(0.f, 0.f, 0.f, 0.f);
            if (brow + row < n)
                v = *(const float4*)&A[(size_t)(brow + row) * K + k0 + q];
            uint4 t;
            t.x = cvt_tf32(v.x); t.y = cvt_tf32(v.y);
            t.z = cvt_tf32(v.z); t.w = cvt_tf32(v.w);
            *(uint4*)&As[row][q] = t;
        }
#pragma unroll
        for (int it = 0; it < 4; ++it) {
            int idx = tid + it * 256;
            int kk = idx >> 5;
            int nn = (idx & 31) * 4;
            float4 v = *(const float4*)&W[(size_t)(k0 + kk) * 128 + nn];
            uint4 t;
            t.x = cvt_tf32(v.x); t.y = cvt_tf32(v.y);
            t.z = cvt_tf32(v.z); t.w = cvt_tf32(v.w);
            *(uint4*)&Ws[kk][nn] = t;
        }
        __syncthreads();

#pragma unroll
        for (int ks = 0; ks < 4; ++ks) {
            const int kb = ks * 8;
            uint32_t af[2][4];
#pragma unroll
            for (int mt = 0; mt < 2; ++mt) {
                int r0 = wm * 32 + mt * 16 + gid;
                af[mt][0] = __float_as_uint(As[r0    ][kb + t4    ]);
                af[mt][1] = __float_as_uint(As[r0 + 8][kb + t4    ]);
                af[mt][2] = __float_as_uint(As[r0    ][kb + t4 + 4]);
                af[mt][3] = __float_as_uint(As[r0 + 8][kb + t4 + 4]);
            }
#pragma unroll
            for (int nt = 0; nt < 8; ++nt) {
                int cb = wn * 64 + nt * 8 + gid;
                uint32_t b0 = __float_as_uint(Ws[kb + t4    ][cb]);
                uint32_t b1 = __float_as_uint(Ws[kb + t4 + 4][cb]);
                mma_tf32(acc[0][nt], af[0], b0, b1);
                mma_tf32(acc[1][nt], af[1], b0, b1);
            }
        }
        __syncthreads();
    }

    // ---- epilogue: store h (fp16) + fused el/er dots (fp32) ----
    float elp[2][2] = {{0.f, 0.f}, {0.f, 0.f}};   // [mt][half]
    float erp[2][2] = {{0.f, 0.f}, {0.f, 0.f}};
#pragma unroll
    for (int mt = 0; mt < 2; ++mt) {
        int r0 = brow + wm * 32 + mt * 16 + gid;
#pragma unroll
        for (int nt = 0; nt < 8; ++nt) {
            int col = wn * 64 + nt * 8 + t4 * 2;
            float a0 = al[col], a1 = al[col + 1];
            float r0v = ar[col], r1v = ar[col + 1];
            elp[mt][0] += acc[mt][nt][0] * a0  + acc[mt][nt][1] * a1;
            erp[mt][0] += acc[mt][nt][0] * r0v + acc[mt][nt][1] * r1v;
            elp[mt][1] += acc[mt][nt][2] * a0  + acc[mt][nt][3] * a1;
            erp[mt][1] += acc[mt][nt][2] * r0v + acc[mt][nt][3] * r1v;
            if (r0 < n)
                H[(size_t)r0 * 64 + (col >> 1)] =
                    __floats2half2_rn(acc[mt][nt][0], acc[mt][nt][1]);
            if (r0 + 8 < n)
                H[(size_t)(r0 + 8) * 64 + (col >> 1)] =
                    __floats2half2_rn(acc[mt][nt][2], acc[mt][nt][3]);
        }
    }
#pragma unroll
    for (int mt = 0; mt < 2; ++mt)
#pragma unroll
        for (int h = 0; h < 2; ++h) {
            float e = elp[mt][h], r = erp[mt][h];
            e += __shfl_xor_sync(0xffffffffu, e, 1);
            e += __shfl_xor_sync(0xffffffffu, e, 2);
            r += __shfl_xor_sync(0xffffffffu, r, 1);
            r += __shfl_xor_sync(0xffffffffu, r, 2);
            elp[mt][h] = e; erp[mt][h] = r;
        }
    if (t4 == 0) {
#pragma unroll
        for (int mt = 0; mt < 2; ++mt)
#pragma unroll
            for (int h = 0; h < 2; ++h) {
                int row = brow + wm * 32 + mt * 16 + h * 8 + gid;
                if (row < n) {
                    float* e = (float*)&elr[row];
                    e[wn]     = elp[mt][h];   // el{head}
                    e[2 + wn] = erp[mt][h];   // er{head}
                }
            }
    }
}

// --------------- fused single-pass softmax + aggregation + ELU --------------
// Warp per dst node. out = (sum_j p_j h_j)/(sum_j p_j + 1e-9) + b, then ELU.
// Each lane walks ALL edges of the row (broadcast csrc/el loads), computes
// p for its own head (1 exp), accumulates p*h_slice and s redundantly.
// Lane l covers features 4l..4l+3 (head = l>>4): two half2 = one 8B load.

__global__ __launch_bounds__(256)
void k_edge(const __half2* __restrict__ h, const int* __restrict__ rowstart,
            const int* __restrict__ csrc, const float4* __restrict__ elr,
            const float* __restrict__ bias, float* __restrict__ out, int n) {
    int w = (blockIdx.x * blockDim.x + threadIdx.x) >> 5;
    int lane = threadIdx.x & 31;
    if (w >= n) return;
    int st = rowstart[w], en = rowstart[w + 1];
    float4 me = elr[w];
    const int head = lane >> 4;
    const float er = head ? me.w : me.z;
    const float2* el2 = (const float2*)elr;   // {el0, el1} at index 2*node
    const uint2* hb = (const uint2*)h;        // 8B per lane-slice

    float s = 0.f;
    float4 acc = make_float4(0.f, 0.f, 0.f, 0.f);

    int j = st;
    for (; j + 1 < en; j += 2) {
        int s0 = csrc[j], s1 = csrc[j + 1];
        float2 ev0 = el2[(size_t)s0 * 2];
        float2 ev1 = el2[(size_t)s1 * 2];
        uint2 hv0 = hb[(size_t)s0 * 32 + lane];
        uint2 hv1 = hb[(size_t)s1 * 32 + lane];
        float e0 = (head ? ev0.y : ev0.x) + er;
        float e1 = (head ? ev1.y : ev1.x) + er;
        e0 = (e0 > 0.f) ? e0 : 0.2f * e0;
        e1 = (e1 > 0.f) ? e1 : 0.2f * e1;
        float p0 = __expf(e0), p1 = __expf(e1);
        s += p0 + p1;
        float2 a01 = __half22float2(*(__half2*)&hv0.x);
        float2 a23 = __half22float2(*(__half2*)&hv0.y);
        float2 b01 = __half22float2(*(__half2*)&hv1.x);
        float2 b23 = __half22float2(*(__half2*)&hv1.y);
        acc.x += p0 * a01.x + p1 * b01.x;
        acc.y += p0 * a01.y + p1 * b01.y;
        acc.z += p0 * a23.x + p1 * b23.x;
        acc.w += p0 * a23.y + p1 * b23.y;
    }
    if (j < en) {
        int s0 = csrc[j];
        float2 ev0 = el2[(size_t)s0 * 2];
        uint2 hv0 = hb[(size_t)s0 * 32 + lane];
        float e0 = (head ? ev0.y : ev0.x) + er;
        e0 = (e0 > 0.f) ? e0 : 0.2f * e0;
        float p0 = __expf(e0);
        s += p0;
        float2 a01 = __half22float2(*(__half2*)&hv0.x);
        float2 a23 = __half22float2(*(__half2*)&hv0.y);
        acc.x += p0 * a01.x; acc.y += p0 * a01.y;
        acc.z += p0 * a23.x; acc.w += p0 * a23.y;
    }

    float inv = 1.f / (s + 1e-9f);
    float4 bv = *(const float4*)&bias[lane * 4];
    acc.x = acc.x * inv + bv.x;
    acc.y = acc.y * inv + bv.y;
    acc.z = acc.z * inv + bv.z;
    acc.w = acc.w * inv + bv.w;
    acc.x = (acc.x > 0.f) ? acc.x : expm1f(acc.x);
    acc.y = (acc.y > 0.f) ? acc.y : expm1f(acc.y);
    acc.z = (acc.z > 0.f) ? acc.z : expm1f(acc.z);
    acc.w = (acc.w > 0.f) ? acc.w : expm1f(acc.w);
    *(float4*)&out[(size_t)w * 128 + lane * 4] = acc;
}

// ------------------------------- final linear -------------------------------

__global__ __launch_bounds__(256)
void k_final(const float* __restrict__ x, const float* __restrict__ Wl,
             const float* __restrict__ bl, float* __restrict__ y, int n) {
    __shared__ float Ws[128][17];
    __shared__ float xs[16][128];
    int tid = threadIdx.x;
    for (int i = tid; i < 2048; i += 256)
        Ws[i >> 4][i & 15] = Wl[i];
    int base = blockIdx.x * 16;
    for (int i = tid; i < 512; i += 256) {
        int nd = i >> 5;
        int kq = (i & 31) * 4;
        int g = base + nd;
        float4 v = make_float4(0.f, 0.f, 0.f, 0.f);
        if (g < n) v = *(const float4*)&x[(size_t)g * 128 + kq];
        *(float4*)&xs[nd][kq] = v;
    }
    __syncthreads();
    int nd = tid >> 4;
    int c  = tid & 15;
    float acc = bl[c];
#pragma unroll 16
    for (int k = 0; k < 128; ++k)
        acc += xs[nd][k] * Ws[k][c];
    int g = base + nd;
    if (g < n) y[(size_t)g * 16 + c] = acc;
}

// --------------------------------- launch ----------------------------------

extern "C" void kernel_launch(void* const* d_in, const int* in_sizes, int n_in,
                              void* d_out, int out_size) {
    const float* features = (const float*)d_in[0];
    const int*   src      = (const int*)  d_in[1];
    const int*   dst      = (const int*)  d_in[2];
    const float* W1  = (const float*)d_in[3];
    const float* al1 = (const float*)d_in[4];
    const float* ar1 = (const float*)d_in[5];
    const float* b1  = (const float*)d_in[6];
    const float* W2  = (const float*)d_in[7];
    const float* al2 = (const float*)d_in[8];
    const float* ar2 = (const float*)d_in[9];
    const float* b2  = (const float*)d_in[10];
    const float* Wl  = (const float*)d_in[11];
    const float* bl  = (const float*)d_in[12];
    float* out = (float*)d_out;

    void *p_hh, *p_x, *p_elr, *p_rs, *p_cur, *p_csrc, *p_bsum, *p_boff;
    cudaGetSymbolAddress(&p_hh,   g_hh);
    cudaGetSymbolAddress(&p_x,    g_x);
    cudaGetSymbolAddress(&p_elr,  g_elr);
    cudaGetSymbolAddress(&p_rs,   g_rowstart);
    cudaGetSymbolAddress(&p_cur,  g_cursor);
    cudaGetSymbolAddress(&p_csrc, g_csrc);
    cudaGetSymbolAddress(&p_bsum, g_bsum);
    cudaGetSymbolAddress(&p_boff, g_boff);

    __half2* hh   = (__half2*)p_hh;
    float*   x_buf = (float*)p_x;
    float4*  elr  = (float4*)p_elr;
    int*     rs   = (int*)p_rs;
    int*     cur  = (int*)p_cur;
    int*     csrc = (int*)p_csrc;
    int*     bsum = (int*)p_bsum;
    int*     boff = (int*)p_boff;

    const int EB  = (NE + 255) / 256;         // 6250
    const int WB  = (NN * 32 + 255) / 256;    // 12500 (warp-per-node)
    const int FB  = (NN + 15) / 16;           // 6250
    const int GTC = (NN + 127) / 128;         // 782

    // ---- CSR build (by dst) ----
    cudaMemsetAsync(cur, 0, NN * sizeof(int));
    k_hist<<<EB, 256>>>(dst, cur, NE);
    k_scan1<<<NB_SCAN, 1024>>>(cur, rs + 1, bsum, NN);
    k_scan2<<<1, 32>>>(bsum, boff, NB_SCAN, rs);
    k_scan3<<<NB_SCAN, 1024>>>(rs + 1, boff, NN);
    cudaMemcpyAsync(cur, rs, NN * sizeof(int), cudaMemcpyDeviceToDevice);
    k_scatter<<<EB, 256>>>(src, dst, cur, csrc, NE);

    // ---- Layer 1 ----
    k_gemm_mma<256><<<GTC, 256>>>(features, W1, al1, ar1, hh, elr, NN);
    k_edge<<<WB, 256>>>(hh, rs, csrc, elr, b1, x_buf, NN);

    // ---- Layer 2 ----
    k_gemm_mma<128><<<GTC, 256>>>(x_buf, W2, al2, ar2, hh, elr, NN);
    k_edge<<<WB, 256>>>(hh, rs, csrc, elr, b2, x_buf, NN);

    // ---- Output head ----
    k_final<<<FB, 256>>>(x_buf, Wl, bl, out, NN);
}